// round 10
// baseline (speedup 1.0000x reference)
#include <cuda_runtime.h>
#include <cuda_bf16.h>
#include <math.h>

typedef unsigned int u32;

#define NN 8192
#define DD 256
#define TK 5
#define TOPC 8

#define MT 128            // tile dim (rows and cols)
#define NSTRIP (NN / MT)  // 64 strips
#define NTILE (NSTRIP * (NSTRIP + 1) / 2)  // 2080
#define KC 64             // k chunk (bf16 elements)
#define NCH (DD / KC)     // 4
#define PITCH 144         // bytes/row for chunk buffers (9*16, ldmatrix conflict-free)
#define CH_BYTES (MT * PITCH)   // 18432
#define SP 132            // Ss pad (floats)
#define NT 512

// ---------------- device scratch ----------------
__device__ float g_psum[32][DD];
__device__ float g_psq[32][DD];
__device__ float g_scale[DD];
__device__ float g_shift[DD];
__device__ float g_HnT[DD * NN];
__device__ float g_Hx[NN * DD];
__device__ float g_F1R[NN * DD];            // exact fp32 normalized rows
__device__ __nv_bfloat16 g_F1bf[NN * DD];   // bf16 rows (mma operands)
__device__ float g_G[NN * DD];
__device__ float g_cv[NN * NSTRIP * TOPC];  // per (row, col-chunk) top-8 dots
__device__ int   g_cj[NN * NSTRIP * TOPC];
__device__ float g_tv[NN * TK];
__device__ int   g_ti[NN * TK];
__device__ float g_dinv[NN];

// ---------------- 1) batchnorm stats ----------------
__global__ void k_stats1(const float* __restrict__ H) {
    int b = blockIdx.x, t = threadIdx.x;
    const float* p = H + (size_t)b * 256 * DD + t;
    float s = 0.f, q = 0.f;
#pragma unroll 8
    for (int r = 0; r < 256; r++) {
        float x = p[(size_t)r * DD];
        s += x; q += x * x;
    }
    g_psum[b][t] = s;
    g_psq[b][t]  = q;
}

__global__ void k_stats2(const float* __restrict__ gamma, const float* __restrict__ beta) {
    int t = threadIdx.x;
    float s = 0.f, q = 0.f;
    for (int b = 0; b < 32; b++) { s += g_psum[b][t]; q += g_psq[b][t]; }
    float mu  = s * (1.f / NN);
    float var = q * (1.f / NN) - mu * mu;
    float sc  = gamma[t] * rsqrtf(var + 1e-5f);
    g_scale[t] = sc;
    g_shift[t] = beta[t] - mu * sc;
}

// ---------------- 3) Hn transposed [k][row] ----------------
__global__ void k_hnT(const float* __restrict__ H) {
    __shared__ float buf[32 * 257];
    int r0 = blockIdx.x * 32;
    int tid = threadIdx.x;
#pragma unroll
    for (int it = 0; it < 8; it++) {
        int e = it * 256 + tid;
        int r = e >> 6;
        int c = (e & 63) * 4;
        float4 h = *(const float4*)(H + (size_t)(r0 + r) * DD + c);
        buf[r * 257 + c + 0] = fmaf(h.x, g_scale[c + 0], g_shift[c + 0]);
        buf[r * 257 + c + 1] = fmaf(h.y, g_scale[c + 1], g_shift[c + 1]);
        buf[r * 257 + c + 2] = fmaf(h.z, g_scale[c + 2], g_shift[c + 2]);
        buf[r * 257 + c + 3] = fmaf(h.w, g_scale[c + 3], g_shift[c + 3]);
    }
    __syncthreads();
    int lane = tid & 31;
    int cbase = tid >> 5;
#pragma unroll
    for (int it = 0; it < 32; it++) {
        int c = cbase + it * 8;
        g_HnT[(size_t)c * NN + r0 + lane] = buf[lane * 257 + c];
    }
}

// ---------------- 4) GEMM: [Hx | G] ----------------
__global__ __launch_bounds__(256) void k_gemm(
    const float* __restrict__ Wt, const float* __restrict__ bt,
    const float* __restrict__ Wo, const float* __restrict__ bo) {
    __shared__ float As[64 * 64];
    __shared__ float Bs[64 * 64];
    int tid = threadIdx.x, tx = tid & 15, ty = tid >> 4;
    int i0 = blockIdx.x * 64;
    int by = blockIdx.y;
    const float* W    = (by < 4) ? Wt : Wo;
    const float* bias = (by < 4) ? bt : bo;
    float* C          = (by < 4) ? g_Hx : g_G;
    int n0 = (by & 3) * 64;

    float acc[4][4] = {};
    for (int kc = 0; kc < 256; kc += 64) {
#pragma unroll
        for (int it = 0; it < 4; it++) {
            int e = it * 256 + tid;
            int k = e >> 4, r4 = e & 15;
            float4 v = *(const float4*)(g_HnT + (size_t)(kc + k) * NN + i0 + r4 * 4);
            *(float4*)(As + k * 64 + r4 * 4) = v;
        }
#pragma unroll
        for (int it = 0; it < 4; it++) {
            int e = it * 256 + tid;
            int k = e >> 4, n4 = e & 15;
            float4 v = *(const float4*)(W + (size_t)(kc + k) * DD + n0 + n4 * 4);
            *(float4*)(Bs + k * 64 + n4 * 4) = v;
        }
        __syncthreads();
#pragma unroll 8
        for (int k = 0; k < 64; k++) {
            float4 a = *(const float4*)(As + k * 64 + ty * 4);
            float4 b = *(const float4*)(Bs + k * 64 + tx * 4);
            acc[0][0] += a.x * b.x; acc[0][1] += a.x * b.y; acc[0][2] += a.x * b.z; acc[0][3] += a.x * b.w;
            acc[1][0] += a.y * b.x; acc[1][1] += a.y * b.y; acc[1][2] += a.y * b.z; acc[1][3] += a.y * b.w;
            acc[2][0] += a.z * b.x; acc[2][1] += a.z * b.y; acc[2][2] += a.z * b.z; acc[2][3] += a.z * b.w;
            acc[3][0] += a.w * b.x; acc[3][1] += a.w * b.y; acc[3][2] += a.w * b.z; acc[3][3] += a.w * b.w;
        }
        __syncthreads();
    }
#pragma unroll
    for (int q = 0; q < 4; q++) {
        int r = i0 + ty * 4 + q;
#pragma unroll
        for (int p = 0; p < 4; p++) {
            int n = n0 + tx * 4 + p;
            C[(size_t)r * DD + n] = acc[q][p] + bias[n];
        }
    }
}

// ---------------- 5) normalize -> F1R (fp32) + F1bf (bf16) ----------------
__global__ void k_norm() {
    int row = blockIdx.x * 8 + (threadIdx.x >> 5);
    int lane = threadIdx.x & 31;
    const float4* src = (const float4*)(g_Hx + (size_t)row * DD);
    float4 x0 = src[lane];
    float4 x1 = src[lane + 32];
    float s = x0.x * x0.x + x0.y * x0.y + x0.z * x0.z + x0.w * x0.w
            + x1.x * x1.x + x1.y * x1.y + x1.z * x1.z + x1.w * x1.w;
#pragma unroll
    for (int o = 16; o > 0; o >>= 1) s += __shfl_xor_sync(0xffffffffu, s, o);
    float inv = 1.f / fmaxf(sqrtf(s), 1e-12f);
    float4 y0 = make_float4(x0.x * inv, x0.y * inv, x0.z * inv, x0.w * inv);
    float4 y1 = make_float4(x1.x * inv, x1.y * inv, x1.z * inv, x1.w * inv);
    ((float4*)(g_F1R + (size_t)row * DD))[lane]      = y0;
    ((float4*)(g_F1R + (size_t)row * DD))[lane + 32] = y1;
    __nv_bfloat162* db = (__nv_bfloat162*)(g_F1bf + (size_t)row * DD);
    db[lane * 2]     = __nv_bfloat162(__float2bfloat16(y0.x), __float2bfloat16(y0.y));
    db[lane * 2 + 1] = __nv_bfloat162(__float2bfloat16(y0.z), __float2bfloat16(y0.w));
    db[64 + lane * 2]     = __nv_bfloat162(__float2bfloat16(y1.x), __float2bfloat16(y1.y));
    db[64 + lane * 2 + 1] = __nv_bfloat162(__float2bfloat16(y1.z), __float2bfloat16(y1.w));
}

__device__ __forceinline__ float affinity(float d) {
    d = fminf(fmaxf(d, -1.f), 1.f);
    float sam = acosf(d);
    float e = expf(-0.2f * sam);
    float a = 1.f / (1.f + expf(-e));
    return fmaxf(a, 0.1f);
}

__device__ __forceinline__ void mma_bf16(float c[4], const u32 a[4], const u32 b[2]) {
    asm volatile(
        "mma.sync.aligned.m16n8k16.row.col.f32.bf16.bf16.f32 "
        "{%0,%1,%2,%3}, {%4,%5,%6,%7}, {%8,%9}, {%0,%1,%2,%3};"
        : "+f"(c[0]), "+f"(c[1]), "+f"(c[2]), "+f"(c[3])
        : "r"(a[0]), "r"(a[1]), "r"(a[2]), "r"(a[3]), "r"(b[0]), "r"(b[1]));
}

__device__ __forceinline__ void ldsm4(u32& r0, u32& r1, u32& r2, u32& r3, u32 addr) {
    asm volatile("ldmatrix.sync.aligned.m8n8.x4.shared.b16 {%0,%1,%2,%3}, [%4];"
                 : "=r"(r0), "=r"(r1), "=r"(r2), "=r"(r3) : "r"(addr));
}

__device__ __forceinline__ void cp16(u32 dst, const void* src) {
    asm volatile("cp.async.cg.shared.global [%0], [%1], 16;" :: "r"(dst), "l"(src));
}

// total-order insert: (v desc, idx asc)
__device__ __forceinline__ void ins8(float* dv, int* dj, float v, int jj) {
    if (v > dv[TOPC - 1] || (v == dv[TOPC - 1] && jj < dj[TOPC - 1])) {
        dv[TOPC - 1] = v; dj[TOPC - 1] = jj;
#pragma unroll
        for (int m = TOPC - 1; m > 0; m--) {
            bool sw = dv[m] > dv[m - 1] || (dv[m] == dv[m - 1] && dj[m] < dj[m - 1]);
            if (sw) {
                float tf = dv[m]; dv[m] = dv[m - 1]; dv[m - 1] = tf;
                int ti = dj[m]; dj[m] = dj[m - 1]; dj[m - 1] = ti;
            }
        }
    }
}

// exchange sorted top-8 with lane^off and merge (both sides converge to same list)
__device__ __forceinline__ void merge_shfl(float* dv, int* dj, int off) {
    float ov[TOPC]; int oj[TOPC];
#pragma unroll
    for (int m = 0; m < TOPC; m++) {
        ov[m] = __shfl_xor_sync(0xffffffffu, dv[m], off);
        oj[m] = __shfl_xor_sync(0xffffffffu, dj[m], off);
    }
#pragma unroll
    for (int m = 0; m < TOPC; m++) ins8(dv, dj, ov[m], oj[m]);
}

// ---------------- 6) symmetric tiles: bf16 HMMA, dual scan ----------------
__global__ __launch_bounds__(NT, 1) void k_symtc() {
    extern __shared__ char smem[];
    u32 sb = (u32)__cvta_generic_to_shared(smem);
    // buffers: fi0, fi1, fj0, fj1 then Ss
    u32 fi_u[2] = { sb, sb + CH_BYTES };
    u32 fj_u[2] = { sb + 2 * CH_BYTES, sb + 3 * CH_BYTES };
    float* Ss = (float*)(smem + 4 * CH_BYTES);

    int tid = threadIdx.x;
    int lane = tid & 31, w = tid >> 5;
    int wm = w & 3, wn = w >> 2;           // 4 x 4 warps over 128 x 128
    int gid = lane >> 2, tig = lane & 3;
    int quad = lane >> 3;
    int qr = (quad & 1) * 8 + (lane & 7);
    int qc = (quad >> 1) * 8;
    int srow = tid >> 2, ssub = tid & 3;   // scans: 4 threads per row/col

    // decode upper-triangular tile
    int t = blockIdx.x, it = 0, rem = t;
    while (rem >= NSTRIP - it) { rem -= NSTRIP - it; it++; }
    int jt = it + rem;
    int i0 = it * MT, j0 = jt * MT;

    // prefetch chunk 0 (Fi rows i0.., Fj rows j0..)
#pragma unroll
    for (int p = 0; p < 2; p++) {
        int e = p * NT + tid;
        int r = e >> 3, c = e & 7;
        cp16(fi_u[0] + r * PITCH + c * 16,
             (const char*)g_F1bf + (size_t)(i0 + r) * 512 + c * 16);
        cp16(fj_u[0] + r * PITCH + c * 16,
             (const char*)g_F1bf + (size_t)(j0 + r) * 512 + c * 16);
    }
    asm volatile("cp.async.commit_group;");

    float acc[2][4][4];
#pragma unroll
    for (int mi = 0; mi < 2; mi++)
#pragma unroll
        for (int ni = 0; ni < 4; ni++)
#pragma unroll
            for (int q = 0; q < 4; q++) acc[mi][ni][q] = 0.f;

    for (int ch = 0; ch < NCH; ch++) {
        if (ch + 1 < NCH) {
            int nb = (ch + 1) & 1;
#pragma unroll
            for (int p = 0; p < 2; p++) {
                int e = p * NT + tid;
                int r = e >> 3, c = e & 7;
                cp16(fi_u[nb] + r * PITCH + c * 16,
                     (const char*)g_F1bf + (size_t)(i0 + r) * 512 + (ch + 1) * 128 + c * 16);
                cp16(fj_u[nb] + r * PITCH + c * 16,
                     (const char*)g_F1bf + (size_t)(j0 + r) * 512 + (ch + 1) * 128 + c * 16);
            }
            asm volatile("cp.async.commit_group;");
            asm volatile("cp.async.wait_group 1;");
        } else {
            asm volatile("cp.async.wait_group 0;");
        }
        __syncthreads();

        u32 fiu = fi_u[ch & 1], fju = fj_u[ch & 1];
#pragma unroll
        for (int s = 0; s < KC / 16; s++) {
            int kB = s * 16;
            u32 a[2][4], b[4][2];
#pragma unroll
            for (int mi = 0; mi < 2; mi++) {
                u32 addr = fiu + (u32)((wm * 32 + mi * 16 + qr) * PITCH + (kB + qc) * 2);
                ldsm4(a[mi][0], a[mi][1], a[mi][2], a[mi][3], addr);
            }
#pragma unroll
            for (int p = 0; p < 2; p++) {
                u32 addr = fju + (u32)((wn * 32 + p * 16 + qr) * PITCH + (kB + qc) * 2);
                u32 r0, r1, r2, r3;
                ldsm4(r0, r1, r2, r3, addr);
                b[2 * p][0] = r0; b[2 * p + 1][0] = r1;
                b[2 * p][1] = r2; b[2 * p + 1][1] = r3;
            }
#pragma unroll
            for (int mi = 0; mi < 2; mi++)
#pragma unroll
                for (int ni = 0; ni < 4; ni++)
                    mma_bf16(acc[mi][ni], a[mi], b[ni]);
        }
        __syncthreads();
    }

    // stage S tile (128 x 128)
#pragma unroll
    for (int mi = 0; mi < 2; mi++) {
        int r = wm * 32 + mi * 16 + gid;
#pragma unroll
        for (int ni = 0; ni < 4; ni++) {
            int c = wn * 32 + ni * 8 + tig * 2;
            *(float2*)(Ss + r * SP + c)       = make_float2(acc[mi][ni][0], acc[mi][ni][1]);
            *(float2*)(Ss + (r + 8) * SP + c) = make_float2(acc[mi][ni][2], acc[mi][ni][3]);
        }
    }
    __syncthreads();

    // ---- row scan: rows of strip it, chunk jt ----
    {
        float dv[TOPC]; int dj[TOPC];
#pragma unroll
        for (int m = 0; m < TOPC; m++) { dv[m] = -3.f; dj[m] = 0x7fffffff; }
#pragma unroll 8
        for (int ii = 0; ii < 32; ii++) {
            int c = ii * 4 + ssub;
            ins8(dv, dj, Ss[srow * SP + c], j0 + c);
        }
        merge_shfl(dv, dj, 1);
        merge_shfl(dv, dj, 2);
        if (ssub == 0) {
            int base = ((i0 + srow) * NSTRIP + jt) * TOPC;
#pragma unroll
            for (int m = 0; m < TOPC; m++) { g_cv[base + m] = dv[m]; g_cj[base + m] = dj[m]; }
        }
    }

    // ---- col scan (off-diagonal): rows of strip jt, chunk it ----
    if (it != jt) {
        float dv[TOPC]; int dj[TOPC];
#pragma unroll
        for (int m = 0; m < TOPC; m++) { dv[m] = -3.f; dj[m] = 0x7fffffff; }
#pragma unroll 8
        for (int ii = 0; ii < 32; ii++) {
            int r = ii * 4 + ssub;
            ins8(dv, dj, Ss[r * SP + srow], i0 + r);
        }
        merge_shfl(dv, dj, 1);
        merge_shfl(dv, dj, 2);
        if (ssub == 0) {
            int base = ((j0 + srow) * NSTRIP + it) * TOPC;
#pragma unroll
            for (int m = 0; m < TOPC; m++) { g_cv[base + m] = dv[m]; g_cj[base + m] = dj[m]; }
        }
    }
}

// ---------------- 7) merge candidates + exact fp32 rescue + A-level top-5 ----------------
__global__ __launch_bounds__(256) void k_merge() {
    int lane = threadIdx.x & 31, w = threadIdx.x >> 5;
    int row = blockIdx.x * 8 + w;

    float dv[TOPC]; int dj[TOPC];
#pragma unroll
    for (int m = 0; m < TOPC; m++) { dv[m] = -3.f; dj[m] = 0x7fffffff; }

    const float* cvp = g_cv + (size_t)row * NSTRIP * TOPC;
    const int*   cjp = g_cj + (size_t)row * NSTRIP * TOPC;
#pragma unroll 4
    for (int tt = 0; tt < NSTRIP * TOPC / 32; tt++) {
        int e = tt * 32 + lane;
        ins8(dv, dj, cvp[e], cjp[e]);
    }
    merge_shfl(dv, dj, 1);
    merge_shfl(dv, dj, 2);
    merge_shfl(dv, dj, 4);
    merge_shfl(dv, dj, 8);
    merge_shfl(dv, dj, 16);

    // 8-lane parallel exact fp32 dot (sequential-k chain, matches all passing rounds)
    int myj = dj[lane & 7];
    const float* ri = g_F1R + (size_t)row * DD;
    const float* rj = g_F1R + (size_t)myj * DD;
    float ex = 0.f;
#pragma unroll 8
    for (int k = 0; k < DD; k++) ex = fmaf(ri[k], rj[k], ex);

    float ev[TOPC];
#pragma unroll
    for (int m = 0; m < TOPC; m++) ev[m] = __shfl_sync(0xffffffffu, ex, m);

    if (lane == 0) {
        int mj[TOPC];
#pragma unroll
        for (int m = 0; m < TOPC; m++) mj[m] = dj[m];

        // sort by (exact dot desc, idx asc)
#pragma unroll
        for (int m = 1; m < TOPC; m++) {
#pragma unroll
            for (int q = TOPC - 1; q >= 1; q--) {
                bool sw = (ev[q] > ev[q - 1]) || (ev[q] == ev[q - 1] && mj[q] < mj[q - 1]);
                if (sw) {
                    float tf = ev[q]; ev[q] = ev[q - 1]; ev[q - 1] = tf;
                    int ti = mj[q]; mj[q] = mj[q - 1]; mj[q - 1] = ti;
                }
            }
        }

        // A values + stable (A desc, idx asc) sort — matches lax.top_k ties
        float av[TOPC];
#pragma unroll
        for (int m = 0; m < TOPC; m++) av[m] = affinity(ev[m]);
#pragma unroll
        for (int m = 1; m < TOPC; m++) {
#pragma unroll
            for (int q = TOPC - 1; q >= 1; q--) {
                bool sw = (av[q] > av[q - 1]) || (av[q] == av[q - 1] && mj[q] < mj[q - 1]);
                if (sw) {
                    float tf = av[q]; av[q] = av[q - 1]; av[q - 1] = tf;
                    int ti = mj[q]; mj[q] = mj[q - 1]; mj[q - 1] = ti;
                }
            }
        }

        float rs = 0.f;
#pragma unroll
        for (int q = 0; q < TK; q++) {
            rs += av[q];
            g_tv[row * TK + q] = av[q];
            g_ti[row * TK + q] = mj[q];
        }
        g_dinv[row] = rsqrtf(rs);
    }
}

// ---------------- 8) scatter sparse A ----------------
__global__ void k_scatterA(float* __restrict__ A) {
    int e = blockIdx.x * blockDim.x + threadIdx.x;
    if (e < NN * TK) {
        int row = e / TK;
        A[(size_t)row * NN + g_ti[e]] = g_tv[e];
    }
}

// ---------------- 9) out = leaky(A_hat @ G) ----------------
__global__ void k_out(float* __restrict__ out) {
    int i = blockIdx.x;
    int c4 = threadIdx.x;
    float di = g_dinv[i];
    float4 acc = make_float4(0.f, 0.f, 0.f, 0.f);
#pragma unroll
    for (int q = 0; q < TK; q++) {
        int j = g_ti[i * TK + q];
        float w = di * g_tv[i * TK + q] * g_dinv[j];
        float4 g = ((const float4*)(g_G + (size_t)j * DD))[c4];
        acc.x += w * g.x; acc.y += w * g.y; acc.z += w * g.z; acc.w += w * g.w;
    }
    acc.x = acc.x >= 0.f ? acc.x : 0.01f * acc.x;
    acc.y = acc.y >= 0.f ? acc.y : 0.01f * acc.y;
    acc.z = acc.z >= 0.f ? acc.z : 0.01f * acc.z;
    acc.w = acc.w >= 0.f ? acc.w : 0.01f * acc.w;
    ((float4*)(out + (size_t)i * DD))[c4] = acc;
}

// ---------------- launcher ----------------
extern "C" void kernel_launch(void* const* d_in, const int* in_sizes, int n_in,
                              void* d_out, int out_size) {
    const float* H     = (const float*)d_in[0];
    const float* gamma = (const float*)d_in[1];
    const float* beta  = (const float*)d_in[2];
    const float* Wt    = (const float*)d_in[3];
    const float* bt    = (const float*)d_in[4];
    const float* Wo    = (const float*)d_in[5];
    const float* bo    = (const float*)d_in[6];

    float* outbuf = (float*)d_out;
    const long long OUT_ND = (long long)NN * DD;
    const long long A_NN   = (long long)NN * NN;

    float* outp = nullptr;
    float* Ap   = nullptr;
    long long osz = (long long)out_size;
    if (osz == OUT_ND + A_NN)      { outp = outbuf; Ap = outbuf + OUT_ND; }
    else if (osz == A_NN)          { Ap = outbuf; }
    else if (osz == OUT_ND)        { outp = outbuf; }
    else                           { outp = outbuf; if (osz >= OUT_ND + A_NN) Ap = outbuf + OUT_ND; }

    const int main_smem = 4 * CH_BYTES + MT * SP * 4;  // 73728 + 67584 = 141312
    cudaFuncSetAttribute(k_symtc, cudaFuncAttributeMaxDynamicSharedMemorySize, main_smem);

    k_stats1<<<32, 256>>>(H);
    k_stats2<<<1, 256>>>(gamma, beta);
    k_hnT<<<NN / 32, 256>>>(H);
    {
        dim3 g(NN / 64, 8);
        k_gemm<<<g, 256>>>(Wt, bt, Wo, bo);
    }
    k_norm<<<NN / 8, 256>>>();
    k_symtc<<<NTILE, NT, main_smem>>>();
    k_merge<<<NN / 8, 256>>>();

    if (Ap) {
        cudaMemsetAsync(Ap, 0, (size_t)A_NN * sizeof(float), 0);
        k_scatterA<<<(NN * TK + 255) / 256, 256>>>(Ap);
    }
    if (outp) {
        k_out<<<NN, 64>>>(outp);
    }
}

// round 14
// speedup vs baseline: 1.3995x; 1.3995x over previous
#include <cuda_runtime.h>
#include <cuda_fp16.h>
#include <math.h>

typedef unsigned int u32;

#define NN 8192
#define DD 256
#define TK 5
#define TOPC 8

#define RT 64        // rows per CTA
#define JT 256       // j tile
#define KC 64        // k chunk (fp16) for Fj
#define NCH (DD / KC)     // 4
#define NJT (NN / JT)     // 32
#define FI_PITCH 528      // bytes/row, 33*16 -> ldmatrix conflict-free
#define FJ_PITCH 144      // bytes/row, 9*16  -> ldmatrix conflict-free
#define FI_BYTES (RT * FI_PITCH)       // 33792
#define FJ_BYTES (JT * FJ_PITCH)       // 36864
#define S_PAD 264
#define NT 512       // threads per CTA (16 warps)

// ---------------- device scratch ----------------
__device__ float g_psum[32][DD];
__device__ float g_psq[32][DD];
__device__ float g_scale[DD];
__device__ float g_shift[DD];
__device__ float g_HnT[DD * NN];
__device__ float g_Hx[NN * DD];
__device__ float g_F1R[NN * DD];   // exact fp32 normalized rows
__device__ __half g_F1h[NN * DD];  // fp16 rows (mma operands)
__device__ float g_G[NN * DD];
__device__ float g_tv[NN * TK];
__device__ int   g_ti[NN * TK];
__device__ float g_dinv[NN];

// ---------------- 1) batchnorm stats ----------------
__global__ void k_stats1(const float* __restrict__ H) {
    int b = blockIdx.x, t = threadIdx.x;
    const float* p = H + (size_t)b * 256 * DD + t;
    float s = 0.f, q = 0.f;
#pragma unroll 8
    for (int r = 0; r < 256; r++) {
        float x = p[(size_t)r * DD];
        s += x; q += x * x;
    }
    g_psum[b][t] = s;
    g_psq[b][t]  = q;
}

__global__ void k_stats2(const float* __restrict__ gamma, const float* __restrict__ beta) {
    int t = threadIdx.x;
    float s = 0.f, q = 0.f;
    for (int b = 0; b < 32; b++) { s += g_psum[b][t]; q += g_psq[b][t]; }
    float mu  = s * (1.f / NN);
    float var = q * (1.f / NN) - mu * mu;
    float sc  = gamma[t] * rsqrtf(var + 1e-5f);
    g_scale[t] = sc;
    g_shift[t] = beta[t] - mu * sc;
}

// ---------------- 3) Hn transposed [k][row] ----------------
__global__ void k_hnT(const float* __restrict__ H) {
    __shared__ float buf[32 * 257];
    int r0 = blockIdx.x * 32;
    int tid = threadIdx.x;
#pragma unroll
    for (int it = 0; it < 8; it++) {
        int e = it * 256 + tid;
        int r = e >> 6;
        int c = (e & 63) * 4;
        float4 h = *(const float4*)(H + (size_t)(r0 + r) * DD + c);
        buf[r * 257 + c + 0] = fmaf(h.x, g_scale[c + 0], g_shift[c + 0]);
        buf[r * 257 + c + 1] = fmaf(h.y, g_scale[c + 1], g_shift[c + 1]);
        buf[r * 257 + c + 2] = fmaf(h.z, g_scale[c + 2], g_shift[c + 2]);
        buf[r * 257 + c + 3] = fmaf(h.w, g_scale[c + 3], g_shift[c + 3]);
    }
    __syncthreads();
    int lane = tid & 31;
    int cbase = tid >> 5;
#pragma unroll
    for (int it = 0; it < 32; it++) {
        int c = cbase + it * 8;
        g_HnT[(size_t)c * NN + r0 + lane] = buf[lane * 257 + c];
    }
}

// ---------------- 4) GEMM: [Hx | G] ----------------
__global__ __launch_bounds__(256) void k_gemm(
    const float* __restrict__ Wt, const float* __restrict__ bt,
    const float* __restrict__ Wo, const float* __restrict__ bo) {
    __shared__ float As[64 * 64];
    __shared__ float Bs[64 * 64];
    int tid = threadIdx.x, tx = tid & 15, ty = tid >> 4;
    int i0 = blockIdx.x * 64;
    int by = blockIdx.y;
    const float* W    = (by < 4) ? Wt : Wo;
    const float* bias = (by < 4) ? bt : bo;
    float* C          = (by < 4) ? g_Hx : g_G;
    int n0 = (by & 3) * 64;

    float acc[4][4] = {};
    for (int kc = 0; kc < 256; kc += 64) {
#pragma unroll
        for (int it = 0; it < 4; it++) {
            int e = it * 256 + tid;
            int k = e >> 4, r4 = e & 15;
            float4 v = *(const float4*)(g_HnT + (size_t)(kc + k) * NN + i0 + r4 * 4);
            *(float4*)(As + k * 64 + r4 * 4) = v;
        }
#pragma unroll
        for (int it = 0; it < 4; it++) {
            int e = it * 256 + tid;
            int k = e >> 4, n4 = e & 15;
            float4 v = *(const float4*)(W + (size_t)(kc + k) * DD + n0 + n4 * 4);
            *(float4*)(Bs + k * 64 + n4 * 4) = v;
        }
        __syncthreads();
#pragma unroll 8
        for (int k = 0; k < 64; k++) {
            float4 a = *(const float4*)(As + k * 64 + ty * 4);
            float4 b = *(const float4*)(Bs + k * 64 + tx * 4);
            acc[0][0] += a.x * b.x; acc[0][1] += a.x * b.y; acc[0][2] += a.x * b.z; acc[0][3] += a.x * b.w;
            acc[1][0] += a.y * b.x; acc[1][1] += a.y * b.y; acc[1][2] += a.y * b.z; acc[1][3] += a.y * b.w;
            acc[2][0] += a.z * b.x; acc[2][1] += a.z * b.y; acc[2][2] += a.z * b.z; acc[2][3] += a.z * b.w;
            acc[3][0] += a.w * b.x; acc[3][1] += a.w * b.y; acc[3][2] += a.w * b.z; acc[3][3] += a.w * b.w;
        }
        __syncthreads();
    }
#pragma unroll
    for (int q = 0; q < 4; q++) {
        int r = i0 + ty * 4 + q;
#pragma unroll
        for (int p = 0; p < 4; p++) {
            int n = n0 + tx * 4 + p;
            C[(size_t)r * DD + n] = acc[q][p] + bias[n];
        }
    }
}

// ---------------- 5) normalize -> F1R (fp32) + F1h (fp16) ----------------
__global__ void k_norm() {
    int row = blockIdx.x * 8 + (threadIdx.x >> 5);
    int lane = threadIdx.x & 31;
    const float4* src = (const float4*)(g_Hx + (size_t)row * DD);
    float4 x0 = src[lane];
    float4 x1 = src[lane + 32];
    float s = x0.x * x0.x + x0.y * x0.y + x0.z * x0.z + x0.w * x0.w
            + x1.x * x1.x + x1.y * x1.y + x1.z * x1.z + x1.w * x1.w;
#pragma unroll
    for (int o = 16; o > 0; o >>= 1) s += __shfl_xor_sync(0xffffffffu, s, o);
    float inv = 1.f / fmaxf(sqrtf(s), 1e-12f);
    float4 y0 = make_float4(x0.x * inv, x0.y * inv, x0.z * inv, x0.w * inv);
    float4 y1 = make_float4(x1.x * inv, x1.y * inv, x1.z * inv, x1.w * inv);
    ((float4*)(g_F1R + (size_t)row * DD))[lane]      = y0;
    ((float4*)(g_F1R + (size_t)row * DD))[lane + 32] = y1;
    __half2* dh = (__half2*)(g_F1h + (size_t)row * DD);
    dh[lane * 2]          = __floats2half2_rn(y0.x, y0.y);
    dh[lane * 2 + 1]      = __floats2half2_rn(y0.z, y0.w);
    dh[64 + lane * 2]     = __floats2half2_rn(y1.x, y1.y);
    dh[64 + lane * 2 + 1] = __floats2half2_rn(y1.z, y1.w);
}

__device__ __forceinline__ float affinity(float d) {
    d = fminf(fmaxf(d, -1.f), 1.f);
    float sam = acosf(d);
    float e = expf(-0.2f * sam);
    float a = 1.f / (1.f + expf(-e));
    return fmaxf(a, 0.1f);
}

__device__ __forceinline__ void mma_f16(float c[4], const u32 a[4], const u32 b[2]) {
    asm volatile(
        "mma.sync.aligned.m16n8k16.row.col.f32.f16.f16.f32 "
        "{%0,%1,%2,%3}, {%4,%5,%6,%7}, {%8,%9}, {%0,%1,%2,%3};"
        : "+f"(c[0]), "+f"(c[1]), "+f"(c[2]), "+f"(c[3])
        : "r"(a[0]), "r"(a[1]), "r"(a[2]), "r"(a[3]), "r"(b[0]), "r"(b[1]));
}

__device__ __forceinline__ void ldsm4(u32& r0, u32& r1, u32& r2, u32& r3, u32 addr) {
    asm volatile("ldmatrix.sync.aligned.m8n8.x4.shared.b16 {%0,%1,%2,%3}, [%4];"
                 : "=r"(r0), "=r"(r1), "=r"(r2), "=r"(r3) : "r"(addr));
}

__device__ __forceinline__ void cp16(u32 dst, const void* src) {
    asm volatile("cp.async.cg.shared.global [%0], [%1], 16;" :: "r"(dst), "l"(src));
}

// total-order insert: (v desc, idx asc) — insertion-order independent selection
__device__ __forceinline__ void ins8(float* dv, int* dj, float v, int jj) {
    if (v > dv[TOPC - 1] || (v == dv[TOPC - 1] && jj < dj[TOPC - 1])) {
        dv[TOPC - 1] = v; dj[TOPC - 1] = jj;
#pragma unroll
        for (int m = TOPC - 1; m > 0; m--) {
            bool sw = dv[m] > dv[m - 1] || (dv[m] == dv[m - 1] && dj[m] < dj[m - 1]);
            if (sw) {
                float tf = dv[m]; dv[m] = dv[m - 1]; dv[m - 1] = tf;
                int ti = dj[m]; dj[m] = dj[m - 1]; dj[m - 1] = ti;
            }
        }
    }
}

// ---------------- 6) main: fp16 HMMA, 16 warps, 3-deep pipeline ----------------
__global__ __launch_bounds__(NT, 1) void k_maintc() {
    extern __shared__ char smem[];
    u32 sb = (u32)__cvta_generic_to_shared(smem);
    u32 fi_u = sb;
    u32 fj_u3[3] = { sb + FI_BYTES, sb + FI_BYTES + FJ_BYTES, sb + FI_BYTES + 2 * FJ_BYTES };
    float* Ss = (float*)(smem + FI_BYTES + 3 * FJ_BYTES);

    int tid = threadIdx.x;
    int lane = tid & 31, w = tid >> 5;
    int wm = w & 3, wn = w >> 2;           // 4 x 4 warps over 64 x 256
    int gid = lane >> 2, tig = lane & 3;
    int quad = lane >> 3;
    int qr = (quad & 1) * 8 + (lane & 7);  // ldmatrix row offset within 16
    int qc = (quad >> 1) * 8;              // ldmatrix k offset within 16
    int i0 = blockIdx.x * RT;
    int srow = tid >> 3, ssub = tid & 7;   // scan: 8 threads per row

    // load Fi DIRECT (known-good path): 64 rows x 512B, pitch 528
#pragma unroll
    for (int it = 0; it < 4; it++) {
        int e = it * NT + tid;
        int r = e >> 5, c = e & 31;
        uint4 v = *(const uint4*)((const char*)g_F1h + (size_t)(i0 + r) * 512 + c * 16);
        *(uint4*)(smem + r * FI_PITCH + c * 16) = v;
    }

    float dv[TOPC]; int dj[TOPC];
#pragma unroll
    for (int m = 0; m < TOPC; m++) { dv[m] = -3.f; dj[m] = 0x7fffffff; }

    // prefetch chunk 0 and chunk 1 (j-tile 0) — two commit groups
#pragma unroll
    for (int it = 0; it < 4; it++) {
        int e = it * NT + tid;
        int r = e >> 3, c = e & 7;
        cp16(fj_u3[0] + r * FJ_PITCH + c * 16,
             (const char*)g_F1h + (size_t)r * 512 + c * 16);
    }
    asm volatile("cp.async.commit_group;");
#pragma unroll
    for (int it = 0; it < 4; it++) {
        int e = it * NT + tid;
        int r = e >> 3, c = e & 7;
        cp16(fj_u3[1] + r * FJ_PITCH + c * 16,
             (const char*)g_F1h + (size_t)r * 512 + 128 + c * 16);
    }
    asm volatile("cp.async.commit_group;");
    __syncthreads();

    for (int jt = 0; jt < NJT; jt++) {
        int j0 = jt * JT;
        float acc[8][4];
#pragma unroll
        for (int ni = 0; ni < 8; ni++)
#pragma unroll
            for (int q = 0; q < 4; q++) acc[ni][q] = 0.f;

        for (int ch = 0; ch < NCH; ch++) {
            int g = jt * NCH + ch;
            bool have_next = (g + 2) < (NJT * NCH);
            if (have_next) {
                int gn = g + 2;
                int njt = gn >> 2, nch = gn & 3;
                int nj0 = njt * JT;
                u32 dstu = fj_u3[gn % 3];
#pragma unroll
                for (int it = 0; it < 4; it++) {
                    int e = it * NT + tid;
                    int r = e >> 3, c = e & 7;
                    cp16(dstu + r * FJ_PITCH + c * 16,
                         (const char*)g_F1h + (size_t)(nj0 + r) * 512 + nch * 128 + c * 16);
                }
                asm volatile("cp.async.commit_group;");
                asm volatile("cp.async.wait_group 2;");
            } else if ((g + 1) < (NJT * NCH)) {
                asm volatile("cp.async.wait_group 1;");
            } else {
                asm volatile("cp.async.wait_group 0;");
            }
            __syncthreads();

            u32 fj_u = fj_u3[g % 3];
#pragma unroll
            for (int s = 0; s < KC / 16; s++) {
                int kA = ch * KC + s * 16;      // global k for Fi
                int kB = s * 16;                // local k in Fj chunk
                u32 a[4], b[8][2];
                {
                    u32 addr = fi_u + (u32)((wm * 16 + qr) * FI_PITCH + (kA + qc) * 2);
                    ldsm4(a[0], a[1], a[2], a[3], addr);
                }
#pragma unroll
                for (int p = 0; p < 4; p++) {
                    u32 addr = fj_u + (u32)((wn * 64 + p * 16 + qr) * FJ_PITCH + (kB + qc) * 2);
                    u32 r0, r1, r2, r3;
                    ldsm4(r0, r1, r2, r3, addr);
                    b[2 * p][0] = r0; b[2 * p + 1][0] = r1;
                    b[2 * p][1] = r2; b[2 * p + 1][1] = r3;
                }
#pragma unroll
                for (int ni = 0; ni < 8; ni++)
                    mma_f16(acc[ni], a, b[ni]);
            }
            __syncthreads();
        }

        // stage S tile (64 x 256)
        {
            int r = wm * 16 + gid;
#pragma unroll
            for (int ni = 0; ni < 8; ni++) {
                int c = wn * 64 + ni * 8 + tig * 2;
                *(float2*)(Ss + r * S_PAD + c)       = make_float2(acc[ni][0], acc[ni][1]);
                *(float2*)(Ss + (r + 8) * S_PAD + c) = make_float2(acc[ni][2], acc[ni][3]);
            }
        }
        __syncthreads();

        // scan: 8 threads/row, float4 chunks (order-free under total-order comparator)
#pragma unroll
        for (int ii = 0; ii < 8; ii++) {
            int c = (ii * 8 + ssub) * 4;
            float4 v4 = *(const float4*)(Ss + srow * S_PAD + c);
            ins8(dv, dj, v4.x, j0 + c);
            ins8(dv, dj, v4.y, j0 + c + 1);
            ins8(dv, dj, v4.z, j0 + c + 2);
            ins8(dv, dj, v4.w, j0 + c + 3);
        }
        __syncthreads();
    }

    // ---- merge 8 scan-threads per row, then exact fp32 rescue ----
    float* cv = Ss;                   // [64][64]
    int*   cj = (int*)(Ss + 64 * 64); // [64][64]
#pragma unroll
    for (int m = 0; m < TOPC; m++) {
        cv[srow * 64 + ssub * TOPC + m] = dv[m];
        cj[srow * 64 + ssub * TOPC + m] = dj[m];
    }
    __syncthreads();

    if (tid < RT) {
        int i = i0 + tid;
        float mv[TOPC]; int mj[TOPC];
#pragma unroll
        for (int m = 0; m < TOPC; m++) { mv[m] = -3.f; mj[m] = 0x7fffffff; }
        for (int c = 0; c < 64; c++)
            ins8(mv, mj, cv[tid * 64 + c], cj[tid * 64 + c]);

        // exact fp32 dots (sequential-k chains — identical to all passing rounds)
        float ev[TOPC];
#pragma unroll
        for (int m = 0; m < TOPC; m++) ev[m] = 0.f;
        const float* ri = g_F1R + (size_t)i * DD;
        for (int k = 0; k < DD; k++) {
            float a = ri[k];
#pragma unroll
            for (int m = 0; m < TOPC; m++)
                ev[m] = fmaf(a, g_F1R[(size_t)mj[m] * DD + k], ev[m]);
        }

        // sort by (exact dot desc, idx asc)
#pragma unroll
        for (int m = 1; m < TOPC; m++) {
#pragma unroll
            for (int q = TOPC - 1; q >= 1; q--) {
                bool sw = (ev[q] > ev[q - 1]) || (ev[q] == ev[q - 1] && mj[q] < mj[q - 1]);
                if (sw) {
                    float tf = ev[q]; ev[q] = ev[q - 1]; ev[q - 1] = tf;
                    int ti = mj[q]; mj[q] = mj[q - 1]; mj[q - 1] = ti;
                }
            }
        }

        // A values + stable (A desc, idx asc) sort — matches lax.top_k ties
        float av[TOPC];
#pragma unroll
        for (int m = 0; m < TOPC; m++) av[m] = affinity(ev[m]);
#pragma unroll
        for (int m = 1; m < TOPC; m++) {
#pragma unroll
            for (int q = TOPC - 1; q >= 1; q--) {
                bool sw = (av[q] > av[q - 1]) || (av[q] == av[q - 1] && mj[q] < mj[q - 1]);
                if (sw) {
                    float tf = av[q]; av[q] = av[q - 1]; av[q - 1] = tf;
                    int ti = mj[q]; mj[q] = mj[q - 1]; mj[q - 1] = ti;
                }
            }
        }

        float rs = 0.f;
#pragma unroll
        for (int q = 0; q < TK; q++) {
            rs += av[q];
            g_tv[i * TK + q] = av[q];
            g_ti[i * TK + q] = mj[q];
        }
        g_dinv[i] = rsqrtf(rs);
    }
}

// ---------------- 7) scatter sparse A ----------------
__global__ void k_scatterA(float* __restrict__ A) {
    int e = blockIdx.x * blockDim.x + threadIdx.x;
    if (e < NN * TK) {
        int row = e / TK;
        A[(size_t)row * NN + g_ti[e]] = g_tv[e];
    }
}

// ---------------- 8) out = leaky(A_hat @ G) ----------------
__global__ void k_out(float* __restrict__ out) {
    int i = blockIdx.x;
    int c4 = threadIdx.x;
    float di = g_dinv[i];
    float4 acc = make_float4(0.f, 0.f, 0.f, 0.f);
#pragma unroll
    for (int q = 0; q < TK; q++) {
        int j = g_ti[i * TK + q];
        float w = di * g_tv[i * TK + q] * g_dinv[j];
        float4 g = ((const float4*)(g_G + (size_t)j * DD))[c4];
        acc.x += w * g.x; acc.y += w * g.y; acc.z += w * g.z; acc.w += w * g.w;
    }
    acc.x = acc.x >= 0.f ? acc.x : 0.01f * acc.x;
    acc.y = acc.y >= 0.f ? acc.y : 0.01f * acc.y;
    acc.z = acc.z >= 0.f ? acc.z : 0.01f * acc.z;
    acc.w = acc.w >= 0.f ? acc.w : 0.01f * acc.w;
    ((float4*)(out + (size_t)i * DD))[c4] = acc;
}

// ---------------- launcher ----------------
extern "C" void kernel_launch(void* const* d_in, const int* in_sizes, int n_in,
                              void* d_out, int out_size) {
    const float* H     = (const float*)d_in[0];
    const float* gamma = (const float*)d_in[1];
    const float* beta  = (const float*)d_in[2];
    const float* Wt    = (const float*)d_in[3];
    const float* bt    = (const float*)d_in[4];
    const float* Wo    = (const float*)d_in[5];
    const float* bo    = (const float*)d_in[6];

    float* outbuf = (float*)d_out;
    const long long OUT_ND = (long long)NN * DD;
    const long long A_NN   = (long long)NN * NN;

    float* outp = nullptr;
    float* Ap   = nullptr;
    long long osz = (long long)out_size;
    if (osz == OUT_ND + A_NN)      { outp = outbuf; Ap = outbuf + OUT_ND; }
    else if (osz == A_NN)          { Ap = outbuf; }
    else if (osz == OUT_ND)        { outp = outbuf; }
    else                           { outp = outbuf; if (osz >= OUT_ND + A_NN) Ap = outbuf + OUT_ND; }

    const int main_smem = FI_BYTES + 3 * FJ_BYTES + RT * S_PAD * 4;  // 211968
    cudaFuncSetAttribute(k_maintc, cudaFuncAttributeMaxDynamicSharedMemorySize, main_smem);

    k_stats1<<<32, 256>>>(H);
    k_stats2<<<1, 256>>>(gamma, beta);
    k_hnT<<<NN / 32, 256>>>(H);
    {
        dim3 g(NN / 64, 8);
        k_gemm<<<g, 256>>>(Wt, bt, Wo, bo);
    }
    k_norm<<<NN / 8, 256>>>();
    k_maintc<<<NN / RT, NT, main_smem>>>();

    if (Ap) {
        cudaMemsetAsync(Ap, 0, (size_t)A_NN * sizeof(float), 0);
        k_scatterA<<<(NN * TK + 255) / 256, 256>>>(Ap);
    }
    if (outp) {
        k_out<<<NN, 64>>>(outp);
    }
}